// round 3
// baseline (speedup 1.0000x reference)
#include <cuda_runtime.h>
#include <cfloat>

#define BB 8
#define CC 64
#define NN 4096
#define OO 64
#define KNB 20
#define FULLMASK 0xffffffffu

// Scratch (device globals: allocation-free per harness rules)
__device__ float g_pd[134217728];   // [B*N, N] pairwise "distance", 537MB
__device__ float g_sq[32768];       // [B*N] squared norms
__device__ float g_P[2097152];      // [B*N, O]  x·(W1-W2)^T
__device__ float g_Q[2097152];      // [B*N, O]  x·W2^T

// ---------------------------------------------------------------------------
// Kernel 1: squared norms. sq[b,n] = sum_c x[b,c,n]^2 (same FMA order as GEMM)
// ---------------------------------------------------------------------------
__global__ void sq_kernel(const float* __restrict__ x) {
    int t = blockIdx.x * blockDim.x + threadIdx.x;   // 0..32767
    int b = t >> 12, n = t & 4095;
    const float* xp = x + (size_t)b * CC * NN + n;
    float s = 0.f;
    #pragma unroll
    for (int c = 0; c < CC; ++c) {
        float v = xp[(size_t)c * NN];
        s = fmaf(v, v, s);
    }
    g_sq[t] = s;
}

// ---------------------------------------------------------------------------
// Kernel 2: P = x·(W1-W2)^T, Q = x·W2^T   (collapses the edge GEMM)
// ---------------------------------------------------------------------------
__global__ __launch_bounds__(256) void pq_kernel(const float* __restrict__ x,
                                                 const float* __restrict__ W) {
    __shared__ float Wa[CC][OO + 1];
    __shared__ float Wb[CC][OO + 1];
    __shared__ float xs[CC][4];
    int tid = threadIdx.x;
    #pragma unroll
    for (int i = 0; i < 16; ++i) {
        int fid = tid + i * 256;
        int o = fid >> 6, c = fid & 63;
        float w1 = W[o * 128 + c];
        float w2 = W[o * 128 + 64 + c];
        Wa[c][o] = w1 - w2;
        Wb[c][o] = w2;
    }
    int nbase = blockIdx.x * 4;
    int b = nbase >> 12;
    int nb = nbase & 4095;
    {
        int c = tid >> 2, j = tid & 3;
        xs[c][j] = x[(size_t)b * CC * NN + (size_t)c * NN + nb + j];
    }
    __syncthreads();
    int o = tid & 63, nl = tid >> 6;
    float p = 0.f, q = 0.f;
    #pragma unroll
    for (int c = 0; c < CC; ++c) {
        float xv = xs[c][nl];
        p = fmaf(xv, Wa[c][o], p);
        q = fmaf(xv, Wb[c][o], q);
    }
    size_t g = (size_t)(nbase + nl);
    g_P[g * OO + o] = p;
    g_Q[g * OO + o] = q;
}

// ---------------------------------------------------------------------------
// Kernel 3: symmetric pd GEMM, compact triangular grid (528 tiles/batch).
// pd[n][m] = 2*x_n·x_m - sq[n] - sq[m]; mirror-stores the transposed tile.
// ---------------------------------------------------------------------------
__global__ __launch_bounds__(256) void pd_gemm_sym(const float* __restrict__ x) {
    // linear tile id -> (nt <= mt), t = mt(mt+1)/2 + nt
    int t = blockIdx.x;
    int mt = (int)((sqrtf(8.f * (float)t + 1.f) - 1.f) * 0.5f);
    while ((mt + 1) * (mt + 2) / 2 <= t) ++mt;
    while (mt * (mt + 1) / 2 > t) --mt;
    int nt = t - mt * (mt + 1) / 2;

    __shared__ float As[CC][128];
    __shared__ float Bs[CC][128];
    __shared__ float sqn[128], sqm[128];

    int b = blockIdx.z;
    int n0 = nt * 128, m0 = mt * 128;
    const float* xb = x + (size_t)b * CC * NN;
    int tid = threadIdx.x;

    #pragma unroll
    for (int i = 0; i < 8; ++i) {
        int fid = tid + i * 256;
        int c = fid >> 5, v = (fid & 31) << 2;
        *(float4*)&As[c][v] = *(const float4*)&xb[(size_t)c * NN + n0 + v];
        *(float4*)&Bs[c][v] = *(const float4*)&xb[(size_t)c * NN + m0 + v];
    }
    if (tid < 128)       sqn[tid]       = g_sq[b * NN + n0 + tid];
    else                 sqm[tid - 128] = g_sq[b * NN + m0 + (tid - 128)];
    __syncthreads();

    int tx = tid & 15, ty = tid >> 4;
    float acc[8][8];
    #pragma unroll
    for (int i = 0; i < 8; ++i)
        #pragma unroll
        for (int j = 0; j < 8; ++j) acc[i][j] = 0.f;

    #pragma unroll 4
    for (int c = 0; c < CC; ++c) {
        float ar[8], br[8];
        *(float4*)&ar[0] = *(float4*)&As[c][ty * 8];
        *(float4*)&ar[4] = *(float4*)&As[c][ty * 8 + 4];
        *(float4*)&br[0] = *(float4*)&Bs[c][tx * 8];
        *(float4*)&br[4] = *(float4*)&Bs[c][tx * 8 + 4];
        #pragma unroll
        for (int i = 0; i < 8; ++i)
            #pragma unroll
            for (int j = 0; j < 8; ++j)
                acc[i][j] = fmaf(ar[i], br[j], acc[i][j]);
    }

    // normal store: tile [n0.., m0..]
    float* outp = g_pd + ((size_t)(b * NN + n0)) * NN + m0;
    #pragma unroll
    for (int i = 0; i < 8; ++i) {
        int r = ty * 8 + i;
        float sn = sqn[r];
        float res[8];
        #pragma unroll
        for (int j = 0; j < 8; ++j)
            res[j] = 2.f * acc[i][j] - sn - sqm[tx * 8 + j];
        *(float4*)&outp[(size_t)r * NN + tx * 8]     = *(float4*)&res[0];
        *(float4*)&outp[(size_t)r * NN + tx * 8 + 4] = *(float4*)&res[4];
    }

    // mirror store: tile [m0.., n0..] (skip on diagonal)
    if (nt != mt) {
        float* outq = g_pd + ((size_t)(b * NN + m0)) * NN + n0;
        #pragma unroll
        for (int j = 0; j < 8; ++j) {
            int rm = tx * 8 + j;
            float sm = sqm[rm];
            float4 lo, hi;
            lo.x = 2.f * acc[0][j] - sqn[ty * 8 + 0] - sm;
            lo.y = 2.f * acc[1][j] - sqn[ty * 8 + 1] - sm;
            lo.z = 2.f * acc[2][j] - sqn[ty * 8 + 2] - sm;
            lo.w = 2.f * acc[3][j] - sqn[ty * 8 + 3] - sm;
            hi.x = 2.f * acc[4][j] - sqn[ty * 8 + 4] - sm;
            hi.y = 2.f * acc[5][j] - sqn[ty * 8 + 5] - sm;
            hi.z = 2.f * acc[6][j] - sqn[ty * 8 + 6] - sm;
            hi.w = 2.f * acc[7][j] - sqn[ty * 8 + 7] - sm;
            *(float4*)&outq[(size_t)rm * NN + ty * 8]     = lo;
            *(float4*)&outq[(size_t)rm * NN + ty * 8 + 4] = hi;
        }
    }
}

// ---------------------------------------------------------------------------
// Kernel 4: warp-per-row two-pass thresholded top-20, fused with gather +
// BN affine + leaky-relu + max-over-k + transposed store.
// Pass 1: lane-local max of 128 elems -> bitonic sort 32 lane-maxes ->
//         T0 = 20th largest (guarantees >=20 elements >= T0).
// Pass 2: re-scan (L2-hot) with gate (v >= T0 && v > vmin), exact insertion.
// ---------------------------------------------------------------------------
__global__ __launch_bounds__(256) void topk_fused(
    const float* __restrict__ gamma, const float* __restrict__ beta,
    const float* __restrict__ rmean, const float* __restrict__ rvar,
    float* __restrict__ out)
{
    int warp = threadIdx.x >> 5, lane = threadIdx.x & 31;
    int row = blockIdx.x * 8 + warp;        // 0..32767
    int b = row >> 12, n = row & 4095;

    const float4* rowp = (const float4*)(g_pd + (size_t)row * NN);

    // ---- Pass 1: lane max over its own 128 elements
    float lmax = -FLT_MAX;
    #pragma unroll 4
    for (int it = 0; it < 32; ++it) {
        float4 v4 = __ldg(&rowp[it * 32 + lane]);
        lmax = fmaxf(fmaxf(fmaxf(lmax, v4.x), v4.y), fmaxf(v4.z, v4.w));
    }
    // bitonic sort 32 lane-maxes ascending across lanes
    float s = lmax;
    #pragma unroll
    for (int k2 = 2; k2 <= 32; k2 <<= 1) {
        #pragma unroll
        for (int j2 = k2 >> 1; j2 > 0; j2 >>= 1) {
            float o = __shfl_xor_sync(FULLMASK, s, j2);
            bool dirAsc = ((lane & k2) == 0);
            bool upper  = ((lane & j2) == 0);
            float mn = fminf(s, o), mx = fmaxf(s, o);
            s = (dirAsc == upper) ? mn : mx;
        }
    }
    float T0 = __shfl_sync(FULLMASK, s, 32 - KNB);   // 20th largest lane-max

    // ---- Pass 2: exact top-20 over candidates v >= T0
    float lv = -FLT_MAX;
    int   li = 0;
    float vmin = -FLT_MAX;   // uniform across warp
    int   minpos = 0;        // uniform across warp

    for (int it = 0; it < 32; ++it) {
        float4 v4 = __ldg(&rowp[it * 32 + lane]);
        float m4 = fmaxf(fmaxf(v4.x, v4.y), fmaxf(v4.z, v4.w));
        if (__ballot_sync(FULLMASK, m4 >= T0 && m4 > vmin) == 0) continue;
        int ibase = (it * 32 + lane) * 4;
        #pragma unroll
        for (int j = 0; j < 4; ++j) {
            float v = (j == 0) ? v4.x : (j == 1) ? v4.y : (j == 2) ? v4.z : v4.w;
            unsigned m = __ballot_sync(FULLMASK, v >= T0 && v > vmin);
            while (m) {
                int lead = __ffs(m) - 1;
                float cv = __shfl_sync(FULLMASK, v, lead);
                int   ci = __shfl_sync(FULLMASK, ibase, lead) + j;
                if (lane == minpos) { lv = cv; li = ci; }
                // recompute warp-uniform (vmin, minpos)
                float t = (lane < KNB) ? lv : FLT_MAX;
                #pragma unroll
                for (int off = 16; off; off >>= 1)
                    t = fminf(t, __shfl_xor_sync(FULLMASK, t, off));
                vmin = t;
                minpos = __ffs(__ballot_sync(FULLMASK, lane < KNB && lv == vmin)) - 1;
                m &= ~(1u << lead);
                m &= __ballot_sync(FULLMASK, v > vmin);
            }
        }
    }

    // ---- fused epilogue: out[b,o,n] = max_k leaky(BN(P[row,o] + Q[idx_k,o]))
    float sc1 = gamma[lane]      * rsqrtf(rvar[lane]      + 1e-5f);
    float sc2 = gamma[lane + 32] * rsqrtf(rvar[lane + 32] + 1e-5f);
    float bi1 = beta[lane]      - rmean[lane]      * sc1;
    float bi2 = beta[lane + 32] - rmean[lane + 32] * sc2;
    float p1 = g_P[(size_t)row * OO + lane];
    float p2 = g_P[(size_t)row * OO + lane + 32];
    const float* Qb = g_Q + (size_t)b * NN * OO;

    float m1 = -FLT_MAX, m2 = -FLT_MAX;
    #pragma unroll
    for (int kk = 0; kk < KNB; ++kk) {
        int nid = __shfl_sync(FULLMASK, li, kk);
        const float* Qr = Qb + (size_t)nid * OO;
        float y1 = (p1 + __ldg(&Qr[lane]))      * sc1 + bi1;
        float y2 = (p2 + __ldg(&Qr[lane + 32])) * sc2 + bi2;
        y1 = (y1 >= 0.f) ? y1 : 0.2f * y1;
        y2 = (y2 >= 0.f) ? y2 : 0.2f * y2;
        m1 = fmaxf(m1, y1);
        m2 = fmaxf(m2, y2);
    }
    out[((size_t)b * OO + lane)      * NN + n] = m1;
    out[((size_t)b * OO + lane + 32) * NN + n] = m2;
}

// ---------------------------------------------------------------------------
extern "C" void kernel_launch(void* const* d_in, const int* in_sizes, int n_in,
                              void* d_out, int out_size) {
    const float* x     = (const float*)d_in[0];
    const float* W     = (const float*)d_in[1];
    const float* gamma = (const float*)d_in[2];
    const float* beta  = (const float*)d_in[3];
    const float* rmean = (const float*)d_in[4];
    const float* rvar  = (const float*)d_in[5];
    float* out = (float*)d_out;

    sq_kernel<<<128, 256>>>(x);
    pq_kernel<<<8192, 256>>>(x, W);
    {
        dim3 grid(528, 1, BB);
        pd_gemm_sym<<<grid, 256>>>(x);
    }
    topk_fused<<<4096, 256>>>(gamma, beta, rmean, rvar, out);
}

// round 4
// speedup vs baseline: 1.1812x; 1.1812x over previous
#include <cuda_runtime.h>
#include <cfloat>

#define BB 8
#define CC 64
#define NN 4096
#define OO 64
#define KNB 20
#define FULLMASK 0xffffffffu

// Scratch (device globals: allocation-free per harness rules)
__device__ float g_pd[134217728];   // [B*N, N] pairwise "distance", 537MB
__device__ float g_cmax[4194304];  // [B*N, 128] per-32-col-chunk max, 16MB
__device__ float g_sq[32768];       // [B*N] squared norms
__device__ float g_P[2097152];      // [B*N, O]  x·(W1-W2)^T
__device__ float g_Q[2097152];      // [B*N, O]  x·W2^T

// ---------------------------------------------------------------------------
// Kernel 1: squared norms. sq[b,n] = sum_c x[b,c,n]^2 (same FMA order as GEMM)
// ---------------------------------------------------------------------------
__global__ void sq_kernel(const float* __restrict__ x) {
    int t = blockIdx.x * blockDim.x + threadIdx.x;   // 0..32767
    int b = t >> 12, n = t & 4095;
    const float* xp = x + (size_t)b * CC * NN + n;
    float s = 0.f;
    #pragma unroll
    for (int c = 0; c < CC; ++c) {
        float v = xp[(size_t)c * NN];
        s = fmaf(v, v, s);
    }
    g_sq[t] = s;
}

// ---------------------------------------------------------------------------
// Kernel 2: P = x·(W1-W2)^T, Q = x·W2^T   (collapses the edge GEMM)
// ---------------------------------------------------------------------------
__global__ __launch_bounds__(256) void pq_kernel(const float* __restrict__ x,
                                                 const float* __restrict__ W) {
    __shared__ float Wa[CC][OO + 1];
    __shared__ float Wb[CC][OO + 1];
    __shared__ float xs[CC][4];
    int tid = threadIdx.x;
    #pragma unroll
    for (int i = 0; i < 16; ++i) {
        int fid = tid + i * 256;
        int o = fid >> 6, c = fid & 63;
        float w1 = W[o * 128 + c];
        float w2 = W[o * 128 + 64 + c];
        Wa[c][o] = w1 - w2;
        Wb[c][o] = w2;
    }
    int nbase = blockIdx.x * 4;
    int b = nbase >> 12;
    int nb = nbase & 4095;
    {
        int c = tid >> 2, j = tid & 3;
        xs[c][j] = x[(size_t)b * CC * NN + (size_t)c * NN + nb + j];
    }
    __syncthreads();
    int o = tid & 63, nl = tid >> 6;
    float p = 0.f, q = 0.f;
    #pragma unroll
    for (int c = 0; c < CC; ++c) {
        float xv = xs[c][nl];
        p = fmaf(xv, Wa[c][o], p);
        q = fmaf(xv, Wb[c][o], q);
    }
    size_t g = (size_t)(nbase + nl);
    g_P[g * OO + o] = p;
    g_Q[g * OO + o] = q;
}

// ---------------------------------------------------------------------------
// Kernel 3: symmetric pd GEMM, compact triangular grid (528 tiles/batch).
// pd[n][m] = 2*x_n·x_m - sq[n] - sq[m]; mirror-stores the transposed tile.
// Also emits per-(row, 32-col-chunk) maxima into g_cmax for topk gating.
// ---------------------------------------------------------------------------
__global__ __launch_bounds__(256) void pd_gemm_sym(const float* __restrict__ x) {
    // linear tile id -> (nt <= mt), t = mt(mt+1)/2 + nt
    int t = blockIdx.x;
    int mt = (int)((sqrtf(8.f * (float)t + 1.f) - 1.f) * 0.5f);
    while ((mt + 1) * (mt + 2) / 2 <= t) ++mt;
    while (mt * (mt + 1) / 2 > t) --mt;
    int nt = t - mt * (mt + 1) / 2;

    __shared__ float As[CC][128];
    __shared__ float Bs[CC][128];
    __shared__ float sqn[128], sqm[128];
    __shared__ float stg[16][128];     // mirror-side chunkmax staging

    int b = blockIdx.z;
    int n0 = nt * 128, m0 = mt * 128;
    const float* xb = x + (size_t)b * CC * NN;
    int tid = threadIdx.x;

    #pragma unroll
    for (int i = 0; i < 8; ++i) {
        int fid = tid + i * 256;
        int c = fid >> 5, v = (fid & 31) << 2;
        *(float4*)&As[c][v] = *(const float4*)&xb[(size_t)c * NN + n0 + v];
        *(float4*)&Bs[c][v] = *(const float4*)&xb[(size_t)c * NN + m0 + v];
    }
    if (tid < 128)       sqn[tid]       = g_sq[b * NN + n0 + tid];
    else                 sqm[tid - 128] = g_sq[b * NN + m0 + (tid - 128)];
    __syncthreads();

    int tx = tid & 15, ty = tid >> 4;
    float acc[8][8];
    #pragma unroll
    for (int i = 0; i < 8; ++i)
        #pragma unroll
        for (int j = 0; j < 8; ++j) acc[i][j] = 0.f;

    #pragma unroll 4
    for (int c = 0; c < CC; ++c) {
        float ar[8], br[8];
        *(float4*)&ar[0] = *(float4*)&As[c][ty * 8];
        *(float4*)&ar[4] = *(float4*)&As[c][ty * 8 + 4];
        *(float4*)&br[0] = *(float4*)&Bs[c][tx * 8];
        *(float4*)&br[4] = *(float4*)&Bs[c][tx * 8 + 4];
        #pragma unroll
        for (int i = 0; i < 8; ++i)
            #pragma unroll
            for (int j = 0; j < 8; ++j)
                acc[i][j] = fmaf(ar[i], br[j], acc[i][j]);
    }

    // normal store: tile [n0.., m0..] + n-side chunk maxima
    float* outp = g_pd + ((size_t)(b * NN + n0)) * NN + m0;
    float* cmn  = g_cmax + ((size_t)(b * NN + n0)) * 128 + (m0 >> 5);
    #pragma unroll
    for (int i = 0; i < 8; ++i) {
        int r = ty * 8 + i;
        float sn = sqn[r];
        float res[8];
        #pragma unroll
        for (int j = 0; j < 8; ++j)
            res[j] = 2.f * acc[i][j] - sn - sqm[tx * 8 + j];
        *(float4*)&outp[(size_t)r * NN + tx * 8]     = *(float4*)&res[0];
        *(float4*)&outp[(size_t)r * NN + tx * 8 + 4] = *(float4*)&res[4];
        // chunk max over this thread's 8 cols, then combine 4 tx within chunk
        float rm = fmaxf(fmaxf(fmaxf(res[0], res[1]), fmaxf(res[2], res[3])),
                         fmaxf(fmaxf(res[4], res[5]), fmaxf(res[6], res[7])));
        rm = fmaxf(rm, __shfl_xor_sync(FULLMASK, rm, 1));
        rm = fmaxf(rm, __shfl_xor_sync(FULLMASK, rm, 2));
        if ((tx & 3) == 0)
            cmn[(size_t)r * 128 + (tx >> 2)] = rm;
    }

    // mirror store: tile [m0.., n0..] + m-side chunk maxima (skip on diagonal)
    if (nt != mt) {
        float* outq = g_pd + ((size_t)(b * NN + m0)) * NN + n0;
        #pragma unroll
        for (int j = 0; j < 8; ++j) {
            int rm = tx * 8 + j;
            float sm = sqm[rm];
            float4 lo, hi;
            lo.x = 2.f * acc[0][j] - sqn[ty * 8 + 0] - sm;
            lo.y = 2.f * acc[1][j] - sqn[ty * 8 + 1] - sm;
            lo.z = 2.f * acc[2][j] - sqn[ty * 8 + 2] - sm;
            lo.w = 2.f * acc[3][j] - sqn[ty * 8 + 3] - sm;
            hi.x = 2.f * acc[4][j] - sqn[ty * 8 + 4] - sm;
            hi.y = 2.f * acc[5][j] - sqn[ty * 8 + 5] - sm;
            hi.z = 2.f * acc[6][j] - sqn[ty * 8 + 6] - sm;
            hi.w = 2.f * acc[7][j] - sqn[ty * 8 + 7] - sm;
            *(float4*)&outq[(size_t)rm * NN + ty * 8]     = lo;
            *(float4*)&outq[(size_t)rm * NN + ty * 8 + 4] = hi;
            // per-thread max over the 8 n-values for this mirror row
            float cm = fmaxf(fmaxf(fmaxf(lo.x, lo.y), fmaxf(lo.z, lo.w)),
                             fmaxf(fmaxf(hi.x, hi.y), fmaxf(hi.z, hi.w)));
            stg[ty][rm] = cm;
        }
        __syncthreads();
        // reduce groups of 4 ty into n-chunk maxima for mirror rows
        if (tid < 128) {
            int col = tid;   // mirror row m0+col
            float* cmm = g_cmax + ((size_t)(b * NN + m0 + col)) * 128 + (n0 >> 5);
            #pragma unroll
            for (int g = 0; g < 4; ++g) {
                float v = fmaxf(fmaxf(stg[g * 4 + 0][col], stg[g * 4 + 1][col]),
                                fmaxf(stg[g * 4 + 2][col], stg[g * 4 + 3][col]));
                cmm[g] = v;
            }
        }
    }
}

// ---------------------------------------------------------------------------
// Kernel 4: warp-per-row top-20 using precomputed chunk maxima:
//   T0 = 20th-largest lane-group max  (guarantees T0 <= 20th-largest element)
//   visit only chunks with chunkmax >= T0 (and > vmin), exact insertion.
// Fused with gather + BN affine + leaky-relu + max-over-k + transposed store.
// ---------------------------------------------------------------------------
__global__ __launch_bounds__(256) void topk_fused(
    const float* __restrict__ gamma, const float* __restrict__ beta,
    const float* __restrict__ rmean, const float* __restrict__ rvar,
    float* __restrict__ out)
{
    int warp = threadIdx.x >> 5, lane = threadIdx.x & 31;
    int row = blockIdx.x * 8 + warp;        // 0..32767
    int b = row >> 12, n = row & 4095;

    const float* cmrow = g_cmax + (size_t)row * 128;
    // lane holds chunks {lane, 32+lane, 64+lane, 96+lane}
    float cm[4];
    #pragma unroll
    for (int j = 0; j < 4; ++j) cm[j] = __ldg(&cmrow[j * 32 + lane]);
    float lmax = fmaxf(fmaxf(cm[0], cm[1]), fmaxf(cm[2], cm[3]));

    // bitonic sort 32 lane-maxes ascending across lanes
    float s = lmax;
    #pragma unroll
    for (int k2 = 2; k2 <= 32; k2 <<= 1) {
        #pragma unroll
        for (int j2 = k2 >> 1; j2 > 0; j2 >>= 1) {
            float o = __shfl_xor_sync(FULLMASK, s, j2);
            bool dirAsc = ((lane & k2) == 0);
            bool upper  = ((lane & j2) == 0);
            float mn = fminf(s, o), mx = fmaxf(s, o);
            s = (dirAsc == upper) ? mn : mx;
        }
    }
    float T0 = __shfl_sync(FULLMASK, s, 32 - KNB);   // 20th largest lane-group max

    // exact top-20 over candidate chunks (ascending chunk order)
    float lv = -FLT_MAX;
    int   li = 0;
    float vmin = -FLT_MAX;   // uniform across warp
    int   minpos = 0;        // uniform across warp
    const float* rowf = g_pd + (size_t)row * NN;

    #pragma unroll
    for (int j = 0; j < 4; ++j) {
        unsigned cmask = __ballot_sync(FULLMASK, cm[j] >= T0);
        while (cmask) {
            int q = __ffs(cmask) - 1;
            cmask &= cmask - 1;
            float cmv = __shfl_sync(FULLMASK, cm[j], q);
            if (cmv <= vmin && vmin > -FLT_MAX) continue;   // list full & can't beat
            int chunk = j * 32 + q;
            float v = __ldcs(&rowf[chunk * 32 + lane]);
            unsigned m = __ballot_sync(FULLMASK, v >= T0 && v > vmin);
            while (m) {
                int lead = __ffs(m) - 1;
                float cv = __shfl_sync(FULLMASK, v, lead);
                int   ci = chunk * 32 + lead;
                if (lane == minpos) { lv = cv; li = ci; }
                // recompute warp-uniform (vmin, minpos)
                float tt = (lane < KNB) ? lv : FLT_MAX;
                #pragma unroll
                for (int off = 16; off; off >>= 1)
                    tt = fminf(tt, __shfl_xor_sync(FULLMASK, tt, off));
                vmin = tt;
                minpos = __ffs(__ballot_sync(FULLMASK, lane < KNB && lv == vmin)) - 1;
                m &= ~(1u << lead);
                m &= __ballot_sync(FULLMASK, v > vmin);
            }
        }
    }

    // ---- fused epilogue: out[b,o,n] = max_k leaky(BN(P[row,o] + Q[idx_k,o]))
    float sc1 = gamma[lane]      * rsqrtf(rvar[lane]      + 1e-5f);
    float sc2 = gamma[lane + 32] * rsqrtf(rvar[lane + 32] + 1e-5f);
    float bi1 = beta[lane]      - rmean[lane]      * sc1;
    float bi2 = beta[lane + 32] - rmean[lane + 32] * sc2;
    float p1 = g_P[(size_t)row * OO + lane];
    float p2 = g_P[(size_t)row * OO + lane + 32];
    const float* Qb = g_Q + (size_t)b * NN * OO;

    float m1 = -FLT_MAX, m2 = -FLT_MAX;
    #pragma unroll
    for (int kk = 0; kk < KNB; ++kk) {
        int nid = __shfl_sync(FULLMASK, li, kk);
        const float* Qr = Qb + (size_t)nid * OO;
        float y1 = (p1 + __ldg(&Qr[lane]))      * sc1 + bi1;
        float y2 = (p2 + __ldg(&Qr[lane + 32])) * sc2 + bi2;
        y1 = (y1 >= 0.f) ? y1 : 0.2f * y1;
        y2 = (y2 >= 0.f) ? y2 : 0.2f * y2;
        m1 = fmaxf(m1, y1);
        m2 = fmaxf(m2, y2);
    }
    out[((size_t)b * OO + lane)      * NN + n] = m1;
    out[((size_t)b * OO + lane + 32) * NN + n] = m2;
}

// ---------------------------------------------------------------------------
extern "C" void kernel_launch(void* const* d_in, const int* in_sizes, int n_in,
                              void* d_out, int out_size) {
    const float* x     = (const float*)d_in[0];
    const float* W     = (const float*)d_in[1];
    const float* gamma = (const float*)d_in[2];
    const float* beta  = (const float*)d_in[3];
    const float* rmean = (const float*)d_in[4];
    const float* rvar  = (const float*)d_in[5];
    float* out = (float*)d_out;

    sq_kernel<<<128, 256>>>(x);
    pq_kernel<<<8192, 256>>>(x, W);
    {
        dim3 grid(528, 1, BB);
        pd_gemm_sym<<<grid, 256>>>(x);
    }
    topk_fused<<<4096, 256>>>(gamma, beta, rmean, rvar, out);
}

// round 6
// speedup vs baseline: 1.2023x; 1.0179x over previous
#include <cuda_runtime.h>
#include <cfloat>
#include <cstdint>

#define BB 8
#define CC 64
#define NN 4096
#define OO 64
#define KNB 20
#define FULLMASK 0xffffffffu

// Scratch (device globals: allocation-free per harness rules)
__device__ float g_pd[134217728];   // [B*N, N] pairwise "distance", 537MB
__device__ float g_cmax[4194304];   // [B*N, 128] per-32-col-chunk max, 16MB
__device__ float g_sq[32768];       // [B*N] squared norms
__device__ float g_P[2097152];      // [B*N, O]  x·(W1-W2)^T
__device__ float g_Q[2097152];      // [B*N, O]  x·W2^T

// packed f32x2 FMA: d = a*b + d, elementwise on two fp32 lanes (IEEE .rn each)
__device__ __forceinline__ void ffma2(unsigned long long& d,
                                      unsigned long long a,
                                      unsigned long long b) {
    asm("fma.rn.f32x2 %0, %1, %2, %0;" : "+l"(d) : "l"(a), "l"(b));
}
__device__ __forceinline__ unsigned long long dup2(float v) {
    unsigned long long r;
    asm("mov.b64 %0, {%1, %1};" : "=l"(r) : "r"(__float_as_uint(v)));
    return r;
}

// ---------------------------------------------------------------------------
// Kernel 1: squared norms. sq[b,n] = sum_c x[b,c,n]^2 (same FMA order as GEMM)
// ---------------------------------------------------------------------------
__global__ void sq_kernel(const float* __restrict__ x) {
    int t = blockIdx.x * blockDim.x + threadIdx.x;   // 0..32767
    int b = t >> 12, n = t & 4095;
    const float* xp = x + (size_t)b * CC * NN + n;
    float s = 0.f;
    #pragma unroll
    for (int c = 0; c < CC; ++c) {
        float v = xp[(size_t)c * NN];
        s = fmaf(v, v, s);
    }
    g_sq[t] = s;
}

// ---------------------------------------------------------------------------
// Kernel 2: P = x·(W1-W2)^T, Q = x·W2^T   (collapses the edge GEMM)
// ---------------------------------------------------------------------------
__global__ __launch_bounds__(256) void pq_kernel(const float* __restrict__ x,
                                                 const float* __restrict__ W) {
    __shared__ float Wa[CC][OO + 1];
    __shared__ float Wb[CC][OO + 1];
    __shared__ float xs[CC][4];
    int tid = threadIdx.x;
    #pragma unroll
    for (int i = 0; i < 16; ++i) {
        int fid = tid + i * 256;
        int o = fid >> 6, c = fid & 63;
        float w1 = W[o * 128 + c];
        float w2 = W[o * 128 + 64 + c];
        Wa[c][o] = w1 - w2;
        Wb[c][o] = w2;
    }
    int nbase = blockIdx.x * 4;
    int b = nbase >> 12;
    int nb = nbase & 4095;
    {
        int c = tid >> 2, j = tid & 3;
        xs[c][j] = x[(size_t)b * CC * NN + (size_t)c * NN + nb + j];
    }
    __syncthreads();
    int o = tid & 63, nl = tid >> 6;
    float p = 0.f, q = 0.f;
    #pragma unroll
    for (int c = 0; c < CC; ++c) {
        float xv = xs[c][nl];
        p = fmaf(xv, Wa[c][o], p);
        q = fmaf(xv, Wb[c][o], q);
    }
    size_t g = (size_t)(nbase + nl);
    g_P[g * OO + o] = p;
    g_Q[g * OO + o] = q;
}

// ---------------------------------------------------------------------------
// Kernel 3: symmetric pd GEMM with packed f32x2 FMA mainloop.
// Triangular grid (528 tiles/batch), mirror-stores, emits per-32-col chunkmax.
// Arithmetic per element identical to scalar FFMA version (same c-order).
// ---------------------------------------------------------------------------
__global__ __launch_bounds__(256) void pd_gemm_sym(const float* __restrict__ x) {
    // linear tile id -> (nt <= mt), t = mt(mt+1)/2 + nt
    int t = blockIdx.x;
    int mt = (int)((sqrtf(8.f * (float)t + 1.f) - 1.f) * 0.5f);
    while ((mt + 1) * (mt + 2) / 2 <= t) ++mt;
    while (mt * (mt + 1) / 2 > t) --mt;
    int nt = t - mt * (mt + 1) / 2;

    __shared__ float As[CC][128];
    __shared__ float Bs[CC][128];
    __shared__ float sqn[128], sqm[128];
    __shared__ float stg[16][128];     // mirror-side chunkmax staging

    int b = blockIdx.z;
    int n0 = nt * 128, m0 = mt * 128;
    const float* xb = x + (size_t)b * CC * NN;
    int tid = threadIdx.x;

    #pragma unroll
    for (int i = 0; i < 8; ++i) {
        int fid = tid + i * 256;
        int c = fid >> 5, v = (fid & 31) << 2;
        *(float4*)&As[c][v] = *(const float4*)&xb[(size_t)c * NN + n0 + v];
        *(float4*)&Bs[c][v] = *(const float4*)&xb[(size_t)c * NN + m0 + v];
    }
    if (tid < 128)       sqn[tid]       = g_sq[b * NN + n0 + tid];
    else                 sqm[tid - 128] = g_sq[b * NN + m0 + (tid - 128)];
    __syncthreads();

    int tx = tid & 15, ty = tid >> 4;

    // packed accumulators: acc2[i][jp] holds cols (2jp, 2jp+1) for row i
    unsigned long long acc2[8][4];
    #pragma unroll
    for (int i = 0; i < 8; ++i)
        #pragma unroll
        for (int jp = 0; jp < 4; ++jp) acc2[i][jp] = 0ull;

    #pragma unroll 4
    for (int c = 0; c < CC; ++c) {
        float ar[8];
        *(float4*)&ar[0] = *(float4*)&As[c][ty * 8];
        *(float4*)&ar[4] = *(float4*)&As[c][ty * 8 + 4];
        ulonglong2 bl = *(ulonglong2*)&Bs[c][tx * 8];
        ulonglong2 bh = *(ulonglong2*)&Bs[c][tx * 8 + 4];
        unsigned long long br2[4] = {bl.x, bl.y, bh.x, bh.y};
        #pragma unroll
        for (int i = 0; i < 8; ++i) {
            unsigned long long ad = dup2(ar[i]);
            #pragma unroll
            for (int jp = 0; jp < 4; ++jp)
                ffma2(acc2[i][jp], ad, br2[jp]);
        }
    }

    // unpack accumulators into acc[i][j]
    float acc[8][8];
    #pragma unroll
    for (int i = 0; i < 8; ++i)
        #pragma unroll
        for (int jp = 0; jp < 4; ++jp) {
            float2 f = *(float2*)&acc2[i][jp];
            acc[i][jp * 2]     = f.x;
            acc[i][jp * 2 + 1] = f.y;
        }

    // normal store: tile [n0.., m0..] + n-side chunk maxima
    float* outp = g_pd + ((size_t)(b * NN + n0)) * NN + m0;
    float* cmn  = g_cmax + ((size_t)(b * NN + n0)) * 128 + (m0 >> 5);
    #pragma unroll
    for (int i = 0; i < 8; ++i) {
        int r = ty * 8 + i;
        float sn = sqn[r];
        float res[8];
        #pragma unroll
        for (int j = 0; j < 8; ++j)
            res[j] = 2.f * acc[i][j] - sn - sqm[tx * 8 + j];
        *(float4*)&outp[(size_t)r * NN + tx * 8]     = *(float4*)&res[0];
        *(float4*)&outp[(size_t)r * NN + tx * 8 + 4] = *(float4*)&res[4];
        float rm = fmaxf(fmaxf(fmaxf(res[0], res[1]), fmaxf(res[2], res[3])),
                         fmaxf(fmaxf(res[4], res[5]), fmaxf(res[6], res[7])));
        rm = fmaxf(rm, __shfl_xor_sync(FULLMASK, rm, 1));
        rm = fmaxf(rm, __shfl_xor_sync(FULLMASK, rm, 2));
        if ((tx & 3) == 0)
            cmn[(size_t)r * 128 + (tx >> 2)] = rm;
    }

    // mirror store: tile [m0.., n0..] + m-side chunk maxima (skip on diagonal)
    if (nt != mt) {
        float* outq = g_pd + ((size_t)(b * NN + m0)) * NN + n0;
        #pragma unroll
        for (int j = 0; j < 8; ++j) {
            int rm = tx * 8 + j;
            float sm = sqm[rm];
            float4 lo, hi;
            lo.x = 2.f * acc[0][j] - sqn[ty * 8 + 0] - sm;
            lo.y = 2.f * acc[1][j] - sqn[ty * 8 + 1] - sm;
            lo.z = 2.f * acc[2][j] - sqn[ty * 8 + 2] - sm;
            lo.w = 2.f * acc[3][j] - sqn[ty * 8 + 3] - sm;
            hi.x = 2.f * acc[4][j] - sqn[ty * 8 + 4] - sm;
            hi.y = 2.f * acc[5][j] - sqn[ty * 8 + 5] - sm;
            hi.z = 2.f * acc[6][j] - sqn[ty * 8 + 6] - sm;
            hi.w = 2.f * acc[7][j] - sqn[ty * 8 + 7] - sm;
            *(float4*)&outq[(size_t)rm * NN + ty * 8]     = lo;
            *(float4*)&outq[(size_t)rm * NN + ty * 8 + 4] = hi;
            float cm = fmaxf(fmaxf(fmaxf(lo.x, lo.y), fmaxf(lo.z, lo.w)),
                             fmaxf(fmaxf(hi.x, hi.y), fmaxf(hi.z, hi.w)));
            stg[ty][rm] = cm;
        }
        __syncthreads();
        if (tid < 128) {
            int col = tid;   // mirror row m0+col
            float* cmm = g_cmax + ((size_t)(b * NN + m0 + col)) * 128 + (n0 >> 5);
            #pragma unroll
            for (int g = 0; g < 4; ++g) {
                float v = fmaxf(fmaxf(stg[g * 4 + 0][col], stg[g * 4 + 1][col]),
                                fmaxf(stg[g * 4 + 2][col], stg[g * 4 + 3][col]));
                cmm[g] = v;
            }
        }
    }
}

// ---------------------------------------------------------------------------
// Kernel 4: warp-per-row top-20 using precomputed chunk maxima:
//   T0 = 20th-largest lane-group max (guarantees T0 <= 20th-largest element)
//   visit only chunks with chunkmax >= T0 (and > vmin), exact insertion.
// Fused with gather + BN affine + leaky-relu + max-over-k + transposed store.
// ---------------------------------------------------------------------------
__global__ __launch_bounds__(256) void topk_fused(
    const float* __restrict__ gamma, const float* __restrict__ beta,
    const float* __restrict__ rmean, const float* __restrict__ rvar,
    float* __restrict__ out)
{
    int warp = threadIdx.x >> 5, lane = threadIdx.x & 31;
    int row = blockIdx.x * 8 + warp;        // 0..32767
    int b = row >> 12, n = row & 4095;

    const float* cmrow = g_cmax + (size_t)row * 128;
    float cm[4];
    #pragma unroll
    for (int j = 0; j < 4; ++j) cm[j] = __ldg(&cmrow[j * 32 + lane]);
    float lmax = fmaxf(fmaxf(cm[0], cm[1]), fmaxf(cm[2], cm[3]));

    // bitonic sort 32 lane-maxes ascending across lanes
    float s = lmax;
    #pragma unroll
    for (int k2 = 2; k2 <= 32; k2 <<= 1) {
        #pragma unroll
        for (int j2 = k2 >> 1; j2 > 0; j2 >>= 1) {
            float o = __shfl_xor_sync(FULLMASK, s, j2);
            bool dirAsc = ((lane & k2) == 0);
            bool upper  = ((lane & j2) == 0);
            float mn = fminf(s, o), mx = fmaxf(s, o);
            s = (dirAsc == upper) ? mn : mx;
        }
    }
    float T0 = __shfl_sync(FULLMASK, s, 32 - KNB);   // 20th largest lane-group max

    float lv = -FLT_MAX;
    int   li = 0;
    float vmin = -FLT_MAX;
    int   minpos = 0;
    const float* rowf = g_pd + (size_t)row * NN;

    #pragma unroll
    for (int j = 0; j < 4; ++j) {
        unsigned cmask = __ballot_sync(FULLMASK, cm[j] >= T0);
        while (cmask) {
            int q = __ffs(cmask) - 1;
            cmask &= cmask - 1;
            float cmv = __shfl_sync(FULLMASK, cm[j], q);
            if (cmv <= vmin && vmin > -FLT_MAX) continue;   // can't beat list
            int chunk = j * 32 + q;
            float v = __ldcs(&rowf[chunk * 32 + lane]);
            unsigned m = __ballot_sync(FULLMASK, v >= T0 && v > vmin);
            while (m) {
                int lead = __ffs(m) - 1;
                float cv = __shfl_sync(FULLMASK, v, lead);
                int   ci = chunk * 32 + lead;
                if (lane == minpos) { lv = cv; li = ci; }
                float tt = (lane < KNB) ? lv : FLT_MAX;
                #pragma unroll
                for (int off = 16; off; off >>= 1)
                    tt = fminf(tt, __shfl_xor_sync(FULLMASK, tt, off));
                vmin = tt;
                minpos = __ffs(__ballot_sync(FULLMASK, lane < KNB && lv == vmin)) - 1;
                m &= ~(1u << lead);
                m &= __ballot_sync(FULLMASK, v > vmin);
            }
        }
    }

    float sc1 = gamma[lane]      * rsqrtf(rvar[lane]      + 1e-5f);
    float sc2 = gamma[lane + 32] * rsqrtf(rvar[lane + 32] + 1e-5f);
    float bi1 = beta[lane]      - rmean[lane]      * sc1;
    float bi2 = beta[lane + 32] - rmean[lane + 32] * sc2;
    float p1 = g_P[(size_t)row * OO + lane];
    float p2 = g_P[(size_t)row * OO + lane + 32];
    const float* Qb = g_Q + (size_t)b * NN * OO;

    float m1 = -FLT_MAX, m2 = -FLT_MAX;
    #pragma unroll
    for (int kk = 0; kk < KNB; ++kk) {
        int nid = __shfl_sync(FULLMASK, li, kk);
        const float* Qr = Qb + (size_t)nid * OO;
        float y1 = (p1 + __ldg(&Qr[lane]))      * sc1 + bi1;
        float y2 = (p2 + __ldg(&Qr[lane + 32])) * sc2 + bi2;
        y1 = (y1 >= 0.f) ? y1 : 0.2f * y1;
        y2 = (y2 >= 0.f) ? y2 : 0.2f * y2;
        m1 = fmaxf(m1, y1);
        m2 = fmaxf(m2, y2);
    }
    out[((size_t)b * OO + lane)      * NN + n] = m1;
    out[((size_t)b * OO + lane + 32) * NN + n] = m2;
}

// ---------------------------------------------------------------------------
extern "C" void kernel_launch(void* const* d_in, const int* in_sizes, int n_in,
                              void* d_out, int out_size) {
    const float* x     = (const float*)d_in[0];
    const float* W     = (const float*)d_in[1];
    const float* gamma = (const float*)d_in[2];
    const float* beta  = (const float*)d_in[3];
    const float* rmean = (const float*)d_in[4];
    const float* rvar  = (const float*)d_in[5];
    float* out = (float*)d_out;

    sq_kernel<<<128, 256>>>(x);
    pq_kernel<<<8192, 256>>>(x, W);
    {
        dim3 grid(528, 1, BB);
        pd_gemm_sym<<<grid, 256>>>(x);
    }
    topk_fused<<<4096, 256>>>(gamma, beta, rmean, rvar, out);
}